// round 1
// baseline (speedup 1.0000x reference)
#include <cuda_runtime.h>

#define N_USERS 100000
#define N_ITEMS 200000
#define N_NODES 300000
#define D       64
#define HYPER   128
#define NNZ_CNT 4000000
#define NODESD  (N_NODES * D)        /* 19,200,000 floats */

#define UB256 391                    /* ceil(100000/256) */
#define IB256 782                    /* ceil(200000/256) */
#define GRID_ROWS (UB256 + IB256)    /* 1173 */

// Scratch (device globals: no allocations allowed)
__device__ float g_h[NODESD];              // current layer h  (76.8 MB)
__device__ float g_P[2 * D * D];           // P_u, P_i = W Wt
__device__ float g_M[2 * D * D];           // per-layer M = P S
__device__ float g_S[2 * 2 * D * D];       // [parity][partition] S accumulators

#define FMA4(acc, s, v) { (acc).x += (s)*(v).x; (acc).y += (s)*(v).y; \
                          (acc).z += (s)*(v).z; (acc).w += (s)*(v).w; }

__device__ __forceinline__ void red_add_v4(float* dst, float4 v) {
    asm volatile("red.global.add.v4.f32 [%0], {%1,%2,%3,%4};"
                 :: "l"(dst), "f"(v.x), "f"(v.y), "f"(v.z), "f"(v.w) : "memory");
}

// ---------------------------------------------------------------------------
// P = W @ W^T per partition (once per launch). grid=(2), block=256.
// ---------------------------------------------------------------------------
__global__ void kP(const float* __restrict__ user_w, const float* __restrict__ item_w) {
    __shared__ float sW[D * 132];   // [64][128] padded to 132 (bank + 16B align)
    const int part = blockIdx.x;
    const float* W = (part == 0) ? user_w : item_w;
    for (int i = threadIdx.x; i < D * HYPER / 4; i += blockDim.x) {
        int r = i >> 5, c4 = i & 31;
        float4 v = __ldg((const float4*)(W + r * HYPER + c4 * 4));
        *(float4*)(sW + r * 132 + c4 * 4) = v;
    }
    __syncthreads();
    const int rg = threadIdx.x >> 4, cg = threadIdx.x & 15;
    const int r0 = rg * 4, c0 = cg * 4;
    float acc[4][4] = {};
    for (int k = 0; k < HYPER; k += 4) {
        float4 a[4], b[4];
#pragma unroll
        for (int i = 0; i < 4; i++) a[i] = *(float4*)(sW + (r0 + i) * 132 + k);
#pragma unroll
        for (int j = 0; j < 4; j++) b[j] = *(float4*)(sW + (c0 + j) * 132 + k);
#pragma unroll
        for (int i = 0; i < 4; i++)
#pragma unroll
            for (int j = 0; j < 4; j++)
                acc[i][j] += a[i].x*b[j].x + a[i].y*b[j].y + a[i].z*b[j].z + a[i].w*b[j].w;
    }
    float* Pout = g_P + part * D * D;
#pragma unroll
    for (int i = 0; i < 4; i++)
#pragma unroll
        for (int j = 0; j < 4; j++)
            Pout[(r0 + i) * D + c0 + j] = acc[i][j];
}

// ---------------------------------------------------------------------------
// M = P @ S per partition. grid=(2), block=256.
// ---------------------------------------------------------------------------
__global__ void kM(int parity) {
    __shared__ float sP[D * 68];
    __shared__ float sS[D * 68];
    const int part = blockIdx.x;
    const float* P = g_P + part * D * D;
    const float* S = g_S + (parity * 2 + part) * D * D;
    for (int i = threadIdx.x; i < D * D / 4; i += blockDim.x) {
        int r = i >> 4, c4 = i & 15;
        *(float4*)(sP + r * 68 + c4 * 4) = *(const float4*)(P + r * D + c4 * 4);
        *(float4*)(sS + r * 68 + c4 * 4) = *(const float4*)(S + r * D + c4 * 4);
    }
    __syncthreads();
    const int rg = threadIdx.x >> 4, cg = threadIdx.x & 15;
    const int r0 = rg * 4, c0 = cg * 4;
    float4 acc[4] = {};
    for (int k = 0; k < D; k += 4) {
        float4 a[4], m[4];
#pragma unroll
        for (int i = 0; i < 4; i++) a[i] = *(float4*)(sP + (r0 + i) * 68 + k);
#pragma unroll
        for (int j = 0; j < 4; j++) m[j] = *(float4*)(sS + (k + j) * 68 + c0);
#pragma unroll
        for (int i = 0; i < 4; i++) {
            FMA4(acc[i], a[i].x, m[0]); FMA4(acc[i], a[i].y, m[1]);
            FMA4(acc[i], a[i].z, m[2]); FMA4(acc[i], a[i].w, m[3]);
        }
    }
    float* Mout = g_M + part * D * D;
#pragma unroll
    for (int i = 0; i < 4; i++) *(float4*)(Mout + (r0 + i) * D + c0) = acc[i];
}

// ---------------------------------------------------------------------------
// Partition mapping helper for row-tiled kernels (block = 256 rows)
// ---------------------------------------------------------------------------
struct PartInfo { int part, rowbase, partEnd, localOff; const float* emb; };

__device__ __forceinline__ PartInfo get_part(int b, const float* ue, const float* ie) {
    PartInfo p;
    if (b < UB256) { p.part = 0; p.rowbase = b * 256; p.partEnd = N_USERS; p.localOff = 0; p.emb = ue; }
    else { p.part = 1; p.rowbase = N_USERS + (b - UB256) * 256; p.partEnd = N_NODES; p.localOff = N_USERS; p.emb = ie; }
    return p;
}

// ---------------------------------------------------------------------------
// K0: h = emb, hidden_sum = emb, accumulate S0 = emb^T emb (per partition)
// grid = 1173, block = 256, 256 rows/block in 4 x 64-row tiles
// ---------------------------------------------------------------------------
__global__ void k0(const float* __restrict__ user_emb, const float* __restrict__ item_emb,
                   float* __restrict__ hidden_sum) {
    __shared__ float sA[64 * D];
    PartInfo p = get_part(blockIdx.x, user_emb, item_emb);
    const int tid = threadIdx.x;
    const int ag = tid >> 4, bg = tid & 15;
    float4 sacc[4] = {};
    for (int t = 0; t < 4; t++) {
        const int tb = p.rowbase + t * 64;
        for (int i = tid; i < 1024; i += 256) {
            int r = i >> 4, c4 = i & 15;
            int gr = tb + r;
            float4 v = make_float4(0.f, 0.f, 0.f, 0.f);
            if (gr < p.partEnd) {
                v = __ldg((const float4*)(p.emb + (size_t)(gr - p.localOff) * D + c4 * 4));
                size_t idx = (size_t)gr * D + c4 * 4;
                *(float4*)(g_h + idx) = v;
                *(float4*)(hidden_sum + idx) = v;
            }
            *(float4*)(sA + r * D + c4 * 4) = v;
        }
        __syncthreads();
#pragma unroll 4
        for (int r = 0; r < 64; r++) {
            float4 a4 = *(float4*)(sA + r * D + ag * 4);
            float4 b4 = *(float4*)(sA + r * D + bg * 4);
            FMA4(sacc[0], a4.x, b4); FMA4(sacc[1], a4.y, b4);
            FMA4(sacc[2], a4.z, b4); FMA4(sacc[3], a4.w, b4);
        }
        __syncthreads();
    }
    float* Sdst = g_S + p.part * D * D;   // parity 0
#pragma unroll
    for (int j = 0; j < 4; j++)
        red_add_v4(Sdst + (ag * 4 + j) * D + bg * 4, sacc[j]);
}

// ---------------------------------------------------------------------------
// SpMM: gcn[row] += val * h[col], 16 lanes per edge, vector red into d_out
// ---------------------------------------------------------------------------
__global__ void kSpmm(const int* __restrict__ rows, const int* __restrict__ cols,
                      const float* __restrict__ vals, float* __restrict__ gcn) {
    const int lane = threadIdx.x & 15;
    long t = (long)blockIdx.x * blockDim.x + threadIdx.x;
    long stride = ((long)gridDim.x * blockDim.x) >> 4;
    for (long e = t >> 4; e < NNZ_CNT; e += stride) {
        int r = __ldg(rows + e);
        int c = __ldg(cols + e);
        float v = __ldg(vals + e);
        float4 hv = *(const float4*)(g_h + (size_t)c * D + lane * 4);
        float4 o = make_float4(hv.x * v, hv.y * v, hv.z * v, hv.w * v);
        red_add_v4(gcn + (size_t)r * D + lane * 4, o);
    }
}

// ---------------------------------------------------------------------------
// Epilogue: hg = emb @ M; h = gcn + hg; hidden_sum += h; write hg output;
//           optionally accumulate S_next = emb^T h_new
// ---------------------------------------------------------------------------
__global__ void kEpi(const float* __restrict__ user_emb, const float* __restrict__ item_emb,
                     const float* __restrict__ gcn, float* __restrict__ hg_out,
                     float* __restrict__ hidden_sum, int do_S, int parity_out) {
    __shared__ float sM[D * D];
    __shared__ float sA[64 * D];
    __shared__ float sH[64 * D];
    PartInfo p = get_part(blockIdx.x, user_emb, item_emb);
    const int tid = threadIdx.x;
    for (int i = tid; i < D * D / 4; i += 256)
        *(float4*)(sM + i * 4) = *(const float4*)(g_M + p.part * D * D + i * 4);
    const int rg = tid >> 4, cg = tid & 15;
    const int r0 = rg * 4, c0 = cg * 4;
    float4 sacc[4] = {};
    for (int t = 0; t < 4; t++) {
        const int tb = p.rowbase + t * 64;
        for (int i = tid; i < 1024; i += 256) {
            int r = i >> 4, c4 = i & 15;
            int gr = tb + r;
            float4 v = make_float4(0.f, 0.f, 0.f, 0.f);
            if (gr < p.partEnd)
                v = __ldg((const float4*)(p.emb + (size_t)(gr - p.localOff) * D + c4 * 4));
            *(float4*)(sA + r * D + c4 * 4) = v;
        }
        __syncthreads();
        float4 acc[4] = {};
        for (int k = 0; k < D; k += 4) {
            float4 a[4], m[4];
#pragma unroll
            for (int i = 0; i < 4; i++) a[i] = *(float4*)(sA + (r0 + i) * D + k);
#pragma unroll
            for (int j = 0; j < 4; j++) m[j] = *(float4*)(sM + (k + j) * D + c0);
#pragma unroll
            for (int i = 0; i < 4; i++) {
                FMA4(acc[i], a[i].x, m[0]); FMA4(acc[i], a[i].y, m[1]);
                FMA4(acc[i], a[i].z, m[2]); FMA4(acc[i], a[i].w, m[3]);
            }
        }
#pragma unroll
        for (int i = 0; i < 4; i++) {
            int gr = tb + r0 + i;
            if (gr < p.partEnd) {
                size_t idx = (size_t)gr * D + c0;
                float4 g = __ldg((const float4*)(gcn + idx));
                *(float4*)(hg_out + idx) = acc[i];
                float4 hn = make_float4(acc[i].x + g.x, acc[i].y + g.y,
                                        acc[i].z + g.z, acc[i].w + g.w);
                *(float4*)(g_h + idx) = hn;
                float4 hs = *(const float4*)(hidden_sum + idx);
                hs.x += hn.x; hs.y += hn.y; hs.z += hn.z; hs.w += hn.w;
                *(float4*)(hidden_sum + idx) = hs;
                if (do_S) *(float4*)(sH + (r0 + i) * D + c0) = hn;
            } else if (do_S) {
                *(float4*)(sH + (r0 + i) * D + c0) = make_float4(0.f, 0.f, 0.f, 0.f);
            }
        }
        __syncthreads();
        if (do_S) {
#pragma unroll 4
            for (int r = 0; r < 64; r++) {
                float4 a4 = *(float4*)(sA + r * D + rg * 4);
                float4 h4 = *(float4*)(sH + r * D + cg * 4);
                FMA4(sacc[0], a4.x, h4); FMA4(sacc[1], a4.y, h4);
                FMA4(sacc[2], a4.z, h4); FMA4(sacc[3], a4.w, h4);
            }
            __syncthreads();
        }
    }
    if (do_S) {
        float* Sdst = g_S + (parity_out * 2 + p.part) * D * D;
#pragma unroll
        for (int j = 0; j < 4; j++)
            red_add_v4(Sdst + (rg * 4 + j) * D + cg * 4, sacc[j]);
    }
}

// ---------------------------------------------------------------------------
extern "C" void kernel_launch(void* const* d_in, const int* in_sizes, int n_in,
                              void* d_out, int out_size) {
    const float* user_emb = (const float*)d_in[0];
    const float* item_emb = (const float*)d_in[1];
    const float* user_w   = (const float*)d_in[2];
    const float* item_w   = (const float*)d_in[3];
    const float* adj_vals = (const float*)d_in[4];
    const int*   adj_rows = (const int*)d_in[5];
    const int*   adj_cols = (const int*)d_in[6];
    float* out = (float*)d_out;

    // d_out layout (floats): [0) hidden_sum(user_out|item_out) 19.2M
    //                        [19.2M) gcn_hidden L0,L1           38.4M
    //                        [57.6M) hgnn_hidden L0,L1          38.4M
    void* sAddr = nullptr;
    cudaGetSymbolAddress(&sAddr, g_S);
    cudaMemsetAsync(sAddr, 0, sizeof(float) * 2 * 2 * D * D);
    cudaMemsetAsync(out + NODESD, 0, sizeof(float) * (size_t)2 * NODESD);

    kP<<<2, 256>>>(user_w, item_w);
    k0<<<GRID_ROWS, 256>>>(user_emb, item_emb, out);

    for (int l = 0; l < 2; l++) {
        float* gcn_l = out + (size_t)NODESD * (1 + l);
        float* hg_l  = out + (size_t)NODESD * (3 + l);
        kM<<<2, 256>>>(l);
        kSpmm<<<2368, 256>>>(adj_rows, adj_cols, adj_vals, gcn_l);
        kEpi<<<GRID_ROWS, 256>>>(user_emb, item_emb, gcn_l, hg_l, out,
                                 (l == 0) ? 1 : 0, l + 1);
    }
}

// round 3
// speedup vs baseline: 1.2204x; 1.2204x over previous
#include <cuda_runtime.h>

#define N_USERS 100000
#define N_ITEMS 200000
#define N_NODES 300000
#define D       64
#define HYPER   128
#define NNZ_CNT 4000000
#define NODESD  (N_NODES * D)        /* 19,200,000 floats */

#define UB256 391                    /* ceil(100000/256) */
#define IB256 782                    /* ceil(200000/256) */
#define GRID_ROWS (UB256 + IB256)    /* 1173 */

#define SCAN_BLOCKS 293              /* ceil(300000/1024) */

// Scratch (device globals: no allocations allowed)
__device__ float g_h[NODESD];              // current layer h  (76.8 MB)
__device__ float g_P[2 * D * D];           // P_u, P_i = W Wt
__device__ float g_M[2 * D * D];           // per-layer M = P S
__device__ float g_S[2 * 2 * D * D];       // [parity][partition] S accumulators
// CSR scratch
__device__ int   g_cnt[N_NODES];           // histogram, then scatter cursor
__device__ int   g_offs[N_NODES + 1];
__device__ int   g_bsum[SCAN_BLOCKS];
__device__ int   g_csr_cols[NNZ_CNT];
__device__ float g_csr_vals[NNZ_CNT];

#define FMA4(acc, s, v) { (acc).x += (s)*(v).x; (acc).y += (s)*(v).y; \
                          (acc).z += (s)*(v).z; (acc).w += (s)*(v).w; }

__device__ __forceinline__ void red_add_v4(float* dst, float4 v) {
    asm volatile("red.global.add.v4.f32 [%0], {%1,%2,%3,%4};"
                 :: "l"(dst), "f"(v.x), "f"(v.y), "f"(v.z), "f"(v.w) : "memory");
}

// ---------------------------------------------------------------------------
// P = W @ W^T per partition (once per launch). grid=(2), block=256.
// ---------------------------------------------------------------------------
__global__ void kP(const float* __restrict__ user_w, const float* __restrict__ item_w) {
    __shared__ float sW[D * 132];
    const int part = blockIdx.x;
    const float* W = (part == 0) ? user_w : item_w;
    for (int i = threadIdx.x; i < D * HYPER / 4; i += blockDim.x) {
        int r = i >> 5, c4 = i & 31;
        float4 v = __ldg((const float4*)(W + r * HYPER + c4 * 4));
        *(float4*)(sW + r * 132 + c4 * 4) = v;
    }
    __syncthreads();
    const int rg = threadIdx.x >> 4, cg = threadIdx.x & 15;
    const int r0 = rg * 4, c0 = cg * 4;
    float acc[4][4] = {};
    for (int k = 0; k < HYPER; k += 4) {
        float4 a[4], b[4];
#pragma unroll
        for (int i = 0; i < 4; i++) a[i] = *(float4*)(sW + (r0 + i) * 132 + k);
#pragma unroll
        for (int j = 0; j < 4; j++) b[j] = *(float4*)(sW + (c0 + j) * 132 + k);
#pragma unroll
        for (int i = 0; i < 4; i++)
#pragma unroll
            for (int j = 0; j < 4; j++)
                acc[i][j] += a[i].x*b[j].x + a[i].y*b[j].y + a[i].z*b[j].z + a[i].w*b[j].w;
    }
    float* Pout = g_P + part * D * D;
#pragma unroll
    for (int i = 0; i < 4; i++)
#pragma unroll
        for (int j = 0; j < 4; j++)
            Pout[(r0 + i) * D + c0 + j] = acc[i][j];
}

// ---------------------------------------------------------------------------
// M = P @ S per partition. grid=(2), block=256.
// ---------------------------------------------------------------------------
__global__ void kM(int parity) {
    __shared__ float sP[D * 68];
    __shared__ float sS[D * 68];
    const int part = blockIdx.x;
    const float* P = g_P + part * D * D;
    const float* S = g_S + (parity * 2 + part) * D * D;
    for (int i = threadIdx.x; i < D * D / 4; i += blockDim.x) {
        int r = i >> 4, c4 = i & 15;
        *(float4*)(sP + r * 68 + c4 * 4) = *(const float4*)(P + r * D + c4 * 4);
        *(float4*)(sS + r * 68 + c4 * 4) = *(const float4*)(S + r * D + c4 * 4);
    }
    __syncthreads();
    const int rg = threadIdx.x >> 4, cg = threadIdx.x & 15;
    const int r0 = rg * 4, c0 = cg * 4;
    float4 acc[4] = {};
    for (int k = 0; k < D; k += 4) {
        float4 a[4], m[4];
#pragma unroll
        for (int i = 0; i < 4; i++) a[i] = *(float4*)(sP + (r0 + i) * 68 + k);
#pragma unroll
        for (int j = 0; j < 4; j++) m[j] = *(float4*)(sS + (k + j) * 68 + c0);
#pragma unroll
        for (int i = 0; i < 4; i++) {
            FMA4(acc[i], a[i].x, m[0]); FMA4(acc[i], a[i].y, m[1]);
            FMA4(acc[i], a[i].z, m[2]); FMA4(acc[i], a[i].w, m[3]);
        }
    }
    float* Mout = g_M + part * D * D;
#pragma unroll
    for (int i = 0; i < 4; i++) *(float4*)(Mout + (r0 + i) * D + c0) = acc[i];
}

// ---------------------------------------------------------------------------
// CSR build: histogram -> exclusive scan (2 levels) -> scatter
// ---------------------------------------------------------------------------
__global__ void kHist(const int* __restrict__ rows) {
    int i = blockIdx.x * blockDim.x + threadIdx.x;
    if (i < NNZ_CNT) atomicAdd(&g_cnt[__ldg(rows + i)], 1);
}

__global__ void kScanA() {
    __shared__ int wsum[32];
    const int t = threadIdx.x;
    int i = blockIdx.x * 1024 + t;
    int v = (i < N_NODES) ? g_cnt[i] : 0;
    int incl = v;
#pragma unroll
    for (int d = 1; d < 32; d <<= 1) {
        int u = __shfl_up_sync(0xffffffffu, incl, d);
        if ((t & 31) >= d) incl += u;
    }
    if ((t & 31) == 31) wsum[t >> 5] = incl;
    __syncthreads();
    if (t < 32) {
        int w = wsum[t];
        int winc = w;
#pragma unroll
        for (int d = 1; d < 32; d <<= 1) {
            int u = __shfl_up_sync(0xffffffffu, winc, d);
            if (t >= d) winc += u;
        }
        wsum[t] = winc - w;
        if (t == 31) g_bsum[blockIdx.x] = winc;
    }
    __syncthreads();
    if (i < N_NODES) g_offs[i] = incl - v + wsum[t >> 5];
}

__global__ void kScanB() {
    __shared__ int wsum[16];
    const int t = threadIdx.x;              // 512 threads
    int v = (t < SCAN_BLOCKS) ? g_bsum[t] : 0;
    int incl = v;
#pragma unroll
    for (int d = 1; d < 32; d <<= 1) {
        int u = __shfl_up_sync(0xffffffffu, incl, d);
        if ((t & 31) >= d) incl += u;
    }
    if ((t & 31) == 31) wsum[t >> 5] = incl;
    __syncthreads();
    if (t < 16) {
        int w = wsum[t];
        int winc = w;
#pragma unroll
        for (int d = 1; d < 16; d <<= 1) {
            int u = __shfl_up_sync(0x0000ffffu, winc, d);
            if (t >= d) winc += u;
        }
        wsum[t] = winc - w;
    }
    __syncthreads();
    if (t < SCAN_BLOCKS) g_bsum[t] = incl - v + wsum[t >> 5];
}

__global__ void kScanC() {
    int i = blockIdx.x * 1024 + threadIdx.x;
    if (i < N_NODES) {
        int o = g_offs[i] + g_bsum[blockIdx.x];
        g_offs[i] = o;
        g_cnt[i] = o;                       // scatter cursor
    }
    if (blockIdx.x == 0 && threadIdx.x == 0) g_offs[N_NODES] = NNZ_CNT;
}

__global__ void kScatter(const int* __restrict__ rows, const int* __restrict__ cols,
                         const float* __restrict__ vals) {
    int i = blockIdx.x * blockDim.x + threadIdx.x;
    if (i >= NNZ_CNT) return;
    int r = __ldg(rows + i);
    int pos = atomicAdd(&g_cnt[r], 1);
    g_csr_cols[pos] = __ldg(cols + i);
    g_csr_vals[pos] = __ldg(vals + i);
}

// ---------------------------------------------------------------------------
// CSR SpMM: one warp per row; halves of the warp process alternate edges,
// 16 lanes x float4 cover D=64; combine halves with shfl; single store.
// ---------------------------------------------------------------------------
__global__ void kSpmmCsr(float* __restrict__ gcn) {
    const int row = (blockIdx.x * blockDim.x + threadIdx.x) >> 5;
    if (row >= N_NODES) return;
    const int lane = threadIdx.x & 31;
    const int half = lane >> 4, l16 = lane & 15;
    const int s = __ldg(&g_offs[row]);
    const int e = __ldg(&g_offs[row + 1]);
    float4 acc = make_float4(0.f, 0.f, 0.f, 0.f);
    for (int j = s + half; j < e; j += 2) {
        int c = __ldg(g_csr_cols + j);
        float v = __ldg(g_csr_vals + j);
        float4 hv = *(const float4*)(g_h + (size_t)c * D + l16 * 4);
        acc.x += v * hv.x; acc.y += v * hv.y; acc.z += v * hv.z; acc.w += v * hv.w;
    }
    acc.x += __shfl_xor_sync(0xffffffffu, acc.x, 16);
    acc.y += __shfl_xor_sync(0xffffffffu, acc.y, 16);
    acc.z += __shfl_xor_sync(0xffffffffu, acc.z, 16);
    acc.w += __shfl_xor_sync(0xffffffffu, acc.w, 16);
    if (half == 0)
        *(float4*)(gcn + (size_t)row * D + l16 * 4) = acc;
}

// ---------------------------------------------------------------------------
// Partition mapping helper for row-tiled kernels (block = 256 rows)
// ---------------------------------------------------------------------------
struct PartInfo { int part, rowbase, partEnd, localOff; const float* emb; };

__device__ __forceinline__ PartInfo get_part(int b, const float* ue, const float* ie) {
    PartInfo p;
    if (b < UB256) { p.part = 0; p.rowbase = b * 256; p.partEnd = N_USERS; p.localOff = 0; p.emb = ue; }
    else { p.part = 1; p.rowbase = N_USERS + (b - UB256) * 256; p.partEnd = N_NODES; p.localOff = N_USERS; p.emb = ie; }
    return p;
}

// ---------------------------------------------------------------------------
// K0: h = emb, hidden_sum = emb, accumulate S0 = emb^T emb (per partition)
// ---------------------------------------------------------------------------
__global__ void k0(const float* __restrict__ user_emb, const float* __restrict__ item_emb,
                   float* __restrict__ hidden_sum) {
    __shared__ float sA[64 * D];
    PartInfo p = get_part(blockIdx.x, user_emb, item_emb);
    const int tid = threadIdx.x;
    const int ag = tid >> 4, bg = tid & 15;
    float4 sacc[4] = {};
    for (int t = 0; t < 4; t++) {
        const int tb = p.rowbase + t * 64;
        for (int i = tid; i < 1024; i += 256) {
            int r = i >> 4, c4 = i & 15;
            int gr = tb + r;
            float4 v = make_float4(0.f, 0.f, 0.f, 0.f);
            if (gr < p.partEnd) {
                v = __ldg((const float4*)(p.emb + (size_t)(gr - p.localOff) * D + c4 * 4));
                size_t idx = (size_t)gr * D + c4 * 4;
                *(float4*)(g_h + idx) = v;
                *(float4*)(hidden_sum + idx) = v;
            }
            *(float4*)(sA + r * D + c4 * 4) = v;
        }
        __syncthreads();
#pragma unroll 4
        for (int r = 0; r < 64; r++) {
            float4 a4 = *(float4*)(sA + r * D + ag * 4);
            float4 b4 = *(float4*)(sA + r * D + bg * 4);
            FMA4(sacc[0], a4.x, b4); FMA4(sacc[1], a4.y, b4);
            FMA4(sacc[2], a4.z, b4); FMA4(sacc[3], a4.w, b4);
        }
        __syncthreads();
    }
    float* Sdst = g_S + p.part * D * D;   // parity 0
#pragma unroll
    for (int j = 0; j < 4; j++)
        red_add_v4(Sdst + (ag * 4 + j) * D + bg * 4, sacc[j]);
}

// ---------------------------------------------------------------------------
// Epilogue: hg = emb @ M; h = gcn + hg; hidden_sum += h; write hg output;
//           optionally accumulate S_next = emb^T h_new
// ---------------------------------------------------------------------------
__global__ void kEpi(const float* __restrict__ user_emb, const float* __restrict__ item_emb,
                     const float* __restrict__ gcn, float* __restrict__ hg_out,
                     float* __restrict__ hidden_sum, int do_S, int parity_out) {
    __shared__ float sM[D * D];
    __shared__ float sA[64 * D];
    __shared__ float sH[64 * D];
    PartInfo p = get_part(blockIdx.x, user_emb, item_emb);
    const int tid = threadIdx.x;
    for (int i = tid; i < D * D / 4; i += 256)
        *(float4*)(sM + i * 4) = *(const float4*)(g_M + p.part * D * D + i * 4);
    const int rg = tid >> 4, cg = tid & 15;
    const int r0 = rg * 4, c0 = cg * 4;
    float4 sacc[4] = {};
    for (int t = 0; t < 4; t++) {
        const int tb = p.rowbase + t * 64;
        for (int i = tid; i < 1024; i += 256) {
            int r = i >> 4, c4 = i & 15;
            int gr = tb + r;
            float4 v = make_float4(0.f, 0.f, 0.f, 0.f);
            if (gr < p.partEnd)
                v = __ldg((const float4*)(p.emb + (size_t)(gr - p.localOff) * D + c4 * 4));
            *(float4*)(sA + r * D + c4 * 4) = v;
        }
        __syncthreads();
        float4 acc[4] = {};
        for (int k = 0; k < D; k += 4) {
            float4 a[4], m[4];
#pragma unroll
            for (int i = 0; i < 4; i++) a[i] = *(float4*)(sA + (r0 + i) * D + k);
#pragma unroll
            for (int j = 0; j < 4; j++) m[j] = *(float4*)(sM + (k + j) * D + c0);
#pragma unroll
            for (int i = 0; i < 4; i++) {
                FMA4(acc[i], a[i].x, m[0]); FMA4(acc[i], a[i].y, m[1]);
                FMA4(acc[i], a[i].z, m[2]); FMA4(acc[i], a[i].w, m[3]);
            }
        }
#pragma unroll
        for (int i = 0; i < 4; i++) {
            int gr = tb + r0 + i;
            if (gr < p.partEnd) {
                size_t idx = (size_t)gr * D + c0;
                float4 g = __ldg((const float4*)(gcn + idx));
                *(float4*)(hg_out + idx) = acc[i];
                float4 hn = make_float4(acc[i].x + g.x, acc[i].y + g.y,
                                        acc[i].z + g.z, acc[i].w + g.w);
                *(float4*)(g_h + idx) = hn;
                float4 hs = *(const float4*)(hidden_sum + idx);
                hs.x += hn.x; hs.y += hn.y; hs.z += hn.z; hs.w += hn.w;
                *(float4*)(hidden_sum + idx) = hs;
                if (do_S) *(float4*)(sH + (r0 + i) * D + c0) = hn;
            } else if (do_S) {
                *(float4*)(sH + (r0 + i) * D + c0) = make_float4(0.f, 0.f, 0.f, 0.f);
            }
        }
        __syncthreads();
        if (do_S) {
#pragma unroll 4
            for (int r = 0; r < 64; r++) {
                float4 a4 = *(float4*)(sA + r * D + rg * 4);
                float4 h4 = *(float4*)(sH + r * D + cg * 4);
                FMA4(sacc[0], a4.x, h4); FMA4(sacc[1], a4.y, h4);
                FMA4(sacc[2], a4.z, h4); FMA4(sacc[3], a4.w, h4);
            }
            __syncthreads();
        }
    }
    if (do_S) {
        float* Sdst = g_S + (parity_out * 2 + p.part) * D * D;
#pragma unroll
        for (int j = 0; j < 4; j++)
            red_add_v4(Sdst + (rg * 4 + j) * D + cg * 4, sacc[j]);
    }
}

// ---------------------------------------------------------------------------
extern "C" void kernel_launch(void* const* d_in, const int* in_sizes, int n_in,
                              void* d_out, int out_size) {
    const float* user_emb = (const float*)d_in[0];
    const float* item_emb = (const float*)d_in[1];
    const float* user_w   = (const float*)d_in[2];
    const float* item_w   = (const float*)d_in[3];
    const float* adj_vals = (const float*)d_in[4];
    const int*   adj_rows = (const int*)d_in[5];
    const int*   adj_cols = (const int*)d_in[6];
    float* out = (float*)d_out;

    // d_out layout (floats): [0) hidden_sum(user_out|item_out) 19.2M
    //                        [19.2M) gcn_hidden L0,L1           38.4M
    //                        [57.6M) hgnn_hidden L0,L1          38.4M
    void* sAddr = nullptr; cudaGetSymbolAddress(&sAddr, g_S);
    cudaMemsetAsync(sAddr, 0, sizeof(float) * 2 * 2 * D * D);
    void* cAddr = nullptr; cudaGetSymbolAddress(&cAddr, g_cnt);
    cudaMemsetAsync(cAddr, 0, sizeof(int) * N_NODES);

    kP<<<2, 256>>>(user_w, item_w);

    const int EB = (NNZ_CNT + 255) / 256;   // 15625
    kHist<<<EB, 256>>>(adj_rows);
    kScanA<<<SCAN_BLOCKS, 1024>>>();
    kScanB<<<1, 512>>>();
    kScanC<<<SCAN_BLOCKS, 1024>>>();
    kScatter<<<EB, 256>>>(adj_rows, adj_cols, adj_vals);

    k0<<<GRID_ROWS, 256>>>(user_emb, item_emb, out);

    for (int l = 0; l < 2; l++) {
        float* gcn_l = out + (size_t)NODESD * (1 + l);
        float* hg_l  = out + (size_t)NODESD * (3 + l);
        kM<<<2, 256>>>(l);
        kSpmmCsr<<<(N_NODES * 32) / 256, 256>>>(gcn_l);
        kEpi<<<GRID_ROWS, 256>>>(user_emb, item_emb, gcn_l, hg_l, out,
                                 (l == 0) ? 1 : 0, l + 1);
    }
}

// round 4
// speedup vs baseline: 1.3413x; 1.0991x over previous
#include <cuda_runtime.h>

#define N_USERS 100000
#define N_ITEMS 200000
#define N_NODES 300000
#define D       64
#define HYPER   128
#define NNZ_CNT 4000000
#define NODESD  (N_NODES * D)        /* 19,200,000 floats */

#define UB256 391                    /* ceil(100000/256) */
#define IB256 782                    /* ceil(200000/256) */
#define GRID_ROWS (UB256 + IB256)    /* 1173 */

#define SCAN_BLOCKS 293              /* ceil(300000/1024) */

typedef unsigned long long u64t;

// Scratch (device globals: no allocations allowed)
__device__ float g_h[NODESD];              // h1 (written by epi0, read by spmm1/epi1)
__device__ float g_P[2 * D * D];           // P_u, P_i = W Wt
__device__ float g_M[2 * D * D];           // per-layer M = P S
__device__ float g_S[2 * 2 * D * D];       // [parity][partition] S accumulators
// CSR scratch
__device__ int   g_cnt[N_NODES];           // histogram, then scatter cursor
__device__ int   g_offs[N_NODES + 1];
__device__ int   g_bsum[SCAN_BLOCKS];
__device__ int2  g_csr[NNZ_CNT];           // (col, val-bits) interleaved

// ---------------- packed f32x2 helpers ----------------
struct p4 { u64t lo, hi; };                // packed float4

__device__ __forceinline__ u64t pk2(float s) {
    u64t r;
    asm("mov.b64 %0, {%1,%1};" : "=l"(r) : "r"(__float_as_uint(s)));
    return r;
}
__device__ __forceinline__ void fma2(u64t& acc, u64t a, u64t b) {
    asm("fma.rn.f32x2 %0, %1, %2, %0;" : "+l"(acc) : "l"(a), "l"(b));
}
__device__ __forceinline__ float4 unpk(p4 v) {
    unsigned x, y, z, w;
    asm("mov.b64 {%0,%1}, %2;" : "=r"(x), "=r"(y) : "l"(v.lo));
    asm("mov.b64 {%0,%1}, %2;" : "=r"(z), "=r"(w) : "l"(v.hi));
    return make_float4(__uint_as_float(x), __uint_as_float(y),
                       __uint_as_float(z), __uint_as_float(w));
}

__device__ __forceinline__ u64t mk_evict_last() {
    u64t pol;
    asm("createpolicy.fractional.L2::evict_last.b64 %0, 1.0;" : "=l"(pol));
    return pol;
}
__device__ __forceinline__ float4 ld_el(const float* p, u64t pol) {
    float4 v;
    asm("ld.global.nc.L2::cache_hint.v4.f32 {%0,%1,%2,%3}, [%4], %5;"
        : "=f"(v.x), "=f"(v.y), "=f"(v.z), "=f"(v.w) : "l"(p), "l"(pol));
    return v;
}
__device__ __forceinline__ void st_el(float* p, float4 v, u64t pol) {
    asm volatile("st.global.L2::cache_hint.v4.f32 [%0], {%1,%2,%3,%4}, %5;"
                 :: "l"(p), "f"(v.x), "f"(v.y), "f"(v.z), "f"(v.w), "l"(pol) : "memory");
}

#define FMA4(acc, s, v) { (acc).x += (s)*(v).x; (acc).y += (s)*(v).y; \
                          (acc).z += (s)*(v).z; (acc).w += (s)*(v).w; }

__device__ __forceinline__ void red_add_v4(float* dst, float4 v) {
    asm volatile("red.global.add.v4.f32 [%0], {%1,%2,%3,%4};"
                 :: "l"(dst), "f"(v.x), "f"(v.y), "f"(v.z), "f"(v.w) : "memory");
}

// ---------------------------------------------------------------------------
// P = W @ W^T per partition. grid=(2), block=256.
// ---------------------------------------------------------------------------
__global__ void kP(const float* __restrict__ user_w, const float* __restrict__ item_w) {
    __shared__ float sW[D * 132];
    const int part = blockIdx.x;
    const float* W = (part == 0) ? user_w : item_w;
    for (int i = threadIdx.x; i < D * HYPER / 4; i += blockDim.x) {
        int r = i >> 5, c4 = i & 31;
        float4 v = __ldg((const float4*)(W + r * HYPER + c4 * 4));
        *(float4*)(sW + r * 132 + c4 * 4) = v;
    }
    __syncthreads();
    const int rg = threadIdx.x >> 4, cg = threadIdx.x & 15;
    const int r0 = rg * 4, c0 = cg * 4;
    float acc[4][4] = {};
    for (int k = 0; k < HYPER; k += 4) {
        float4 a[4], b[4];
#pragma unroll
        for (int i = 0; i < 4; i++) a[i] = *(float4*)(sW + (r0 + i) * 132 + k);
#pragma unroll
        for (int j = 0; j < 4; j++) b[j] = *(float4*)(sW + (c0 + j) * 132 + k);
#pragma unroll
        for (int i = 0; i < 4; i++)
#pragma unroll
            for (int j = 0; j < 4; j++)
                acc[i][j] += a[i].x*b[j].x + a[i].y*b[j].y + a[i].z*b[j].z + a[i].w*b[j].w;
    }
    float* Pout = g_P + part * D * D;
#pragma unroll
    for (int i = 0; i < 4; i++)
#pragma unroll
        for (int j = 0; j < 4; j++)
            Pout[(r0 + i) * D + c0 + j] = acc[i][j];
}

// ---------------------------------------------------------------------------
// M = P @ S per partition. grid=(2), block=256.
// ---------------------------------------------------------------------------
__global__ void kM(int parity) {
    __shared__ float sP[D * 68];
    __shared__ float sS[D * 68];
    const int part = blockIdx.x;
    const float* P = g_P + part * D * D;
    const float* S = g_S + (parity * 2 + part) * D * D;
    for (int i = threadIdx.x; i < D * D / 4; i += blockDim.x) {
        int r = i >> 4, c4 = i & 15;
        *(float4*)(sP + r * 68 + c4 * 4) = *(const float4*)(P + r * D + c4 * 4);
        *(float4*)(sS + r * 68 + c4 * 4) = *(const float4*)(S + r * D + c4 * 4);
    }
    __syncthreads();
    const int rg = threadIdx.x >> 4, cg = threadIdx.x & 15;
    const int r0 = rg * 4, c0 = cg * 4;
    float4 acc[4] = {};
    for (int k = 0; k < D; k += 4) {
        float4 a[4], m[4];
#pragma unroll
        for (int i = 0; i < 4; i++) a[i] = *(float4*)(sP + (r0 + i) * 68 + k);
#pragma unroll
        for (int j = 0; j < 4; j++) m[j] = *(float4*)(sS + (k + j) * 68 + c0);
#pragma unroll
        for (int i = 0; i < 4; i++) {
            FMA4(acc[i], a[i].x, m[0]); FMA4(acc[i], a[i].y, m[1]);
            FMA4(acc[i], a[i].z, m[2]); FMA4(acc[i], a[i].w, m[3]);
        }
    }
    float* Mout = g_M + part * D * D;
#pragma unroll
    for (int i = 0; i < 4; i++) *(float4*)(Mout + (r0 + i) * D + c0) = acc[i];
}

// ---------------------------------------------------------------------------
// CSR build: histogram -> exclusive scan (2 levels) -> scatter
// ---------------------------------------------------------------------------
__global__ void kHist(const int* __restrict__ rows) {
    int i = blockIdx.x * blockDim.x + threadIdx.x;
    if (i < NNZ_CNT) atomicAdd(&g_cnt[__ldg(rows + i)], 1);
}

__global__ void kScanA() {
    __shared__ int wsum[32];
    const int t = threadIdx.x;
    int i = blockIdx.x * 1024 + t;
    int v = (i < N_NODES) ? g_cnt[i] : 0;
    int incl = v;
#pragma unroll
    for (int d = 1; d < 32; d <<= 1) {
        int u = __shfl_up_sync(0xffffffffu, incl, d);
        if ((t & 31) >= d) incl += u;
    }
    if ((t & 31) == 31) wsum[t >> 5] = incl;
    __syncthreads();
    if (t < 32) {
        int w = wsum[t];
        int winc = w;
#pragma unroll
        for (int d = 1; d < 32; d <<= 1) {
            int u = __shfl_up_sync(0xffffffffu, winc, d);
            if (t >= d) winc += u;
        }
        wsum[t] = winc - w;
        if (t == 31) g_bsum[blockIdx.x] = winc;
    }
    __syncthreads();
    if (i < N_NODES) g_offs[i] = incl - v + wsum[t >> 5];
}

__global__ void kScanB() {
    __shared__ int wsum[16];
    const int t = threadIdx.x;              // 512 threads
    int v = (t < SCAN_BLOCKS) ? g_bsum[t] : 0;
    int incl = v;
#pragma unroll
    for (int d = 1; d < 32; d <<= 1) {
        int u = __shfl_up_sync(0xffffffffu, incl, d);
        if ((t & 31) >= d) incl += u;
    }
    if ((t & 31) == 31) wsum[t >> 5] = incl;
    __syncthreads();
    if (t < 16) {
        int w = wsum[t];
        int winc = w;
#pragma unroll
        for (int d = 1; d < 16; d <<= 1) {
            int u = __shfl_up_sync(0x0000ffffu, winc, d);
            if (t >= d) winc += u;
        }
        wsum[t] = winc - w;
    }
    __syncthreads();
    if (t < SCAN_BLOCKS) g_bsum[t] = incl - v + wsum[t >> 5];
}

__global__ void kScanC() {
    int i = blockIdx.x * 1024 + threadIdx.x;
    if (i < N_NODES) {
        int o = g_offs[i] + g_bsum[blockIdx.x];
        g_offs[i] = o;
        g_cnt[i] = o;                       // scatter cursor
    }
    if (blockIdx.x == 0 && threadIdx.x == 0) g_offs[N_NODES] = NNZ_CNT;
}

__global__ void kScatter(const int* __restrict__ rows, const int* __restrict__ cols,
                         const float* __restrict__ vals) {
    int i = blockIdx.x * blockDim.x + threadIdx.x;
    if (i >= NNZ_CNT) return;
    int r = __ldg(rows + i);
    int pos = atomicAdd(&g_cnt[r], 1);
    g_csr[pos] = make_int2(__ldg(cols + i), __float_as_int(__ldg(vals + i)));
}

// ---------------------------------------------------------------------------
// CSR SpMM, one warp per row, evict_last gathers, __ldcs on CSR stream.
// Layer 0 gathers straight from (user_emb|item_emb); layer 1 from g_h.
// ---------------------------------------------------------------------------
__global__ void __launch_bounds__(256) kSpmm0(const float* __restrict__ user_emb,
                                              const float* __restrict__ item_emb,
                                              float* __restrict__ gcn) {
    const int row = (blockIdx.x * blockDim.x + threadIdx.x) >> 5;
    if (row >= N_NODES) return;
    const int lane = threadIdx.x & 31;
    const int half = lane >> 4, l16 = lane & 15;
    const u64t pol = mk_evict_last();
    const int s = __ldg(&g_offs[row]);
    const int e = __ldg(&g_offs[row + 1]);
    float4 acc = make_float4(0.f, 0.f, 0.f, 0.f);
    for (int j = s + half; j < e; j += 2) {
        int2 cv = __ldcs(&g_csr[j]);
        float v = __int_as_float(cv.y);
        const float* base = (cv.x < N_USERS)
            ? user_emb + (size_t)cv.x * D
            : item_emb + (size_t)(cv.x - N_USERS) * D;
        float4 hv = ld_el(base + l16 * 4, pol);
        acc.x += v * hv.x; acc.y += v * hv.y; acc.z += v * hv.z; acc.w += v * hv.w;
    }
    acc.x += __shfl_xor_sync(0xffffffffu, acc.x, 16);
    acc.y += __shfl_xor_sync(0xffffffffu, acc.y, 16);
    acc.z += __shfl_xor_sync(0xffffffffu, acc.z, 16);
    acc.w += __shfl_xor_sync(0xffffffffu, acc.w, 16);
    if (half == 0)
        *(float4*)(gcn + (size_t)row * D + l16 * 4) = acc;
}

__global__ void __launch_bounds__(256) kSpmm1(float* __restrict__ gcn) {
    const int row = (blockIdx.x * blockDim.x + threadIdx.x) >> 5;
    if (row >= N_NODES) return;
    const int lane = threadIdx.x & 31;
    const int half = lane >> 4, l16 = lane & 15;
    const u64t pol = mk_evict_last();
    const int s = __ldg(&g_offs[row]);
    const int e = __ldg(&g_offs[row + 1]);
    float4 acc = make_float4(0.f, 0.f, 0.f, 0.f);
    for (int j = s + half; j < e; j += 2) {
        int2 cv = __ldcs(&g_csr[j]);
        float v = __int_as_float(cv.y);
        float4 hv = ld_el(g_h + (size_t)cv.x * D + l16 * 4, pol);
        acc.x += v * hv.x; acc.y += v * hv.y; acc.z += v * hv.z; acc.w += v * hv.w;
    }
    acc.x += __shfl_xor_sync(0xffffffffu, acc.x, 16);
    acc.y += __shfl_xor_sync(0xffffffffu, acc.y, 16);
    acc.z += __shfl_xor_sync(0xffffffffu, acc.z, 16);
    acc.w += __shfl_xor_sync(0xffffffffu, acc.w, 16);
    if (half == 0)
        *(float4*)(gcn + (size_t)row * D + l16 * 4) = acc;
}

// ---------------------------------------------------------------------------
// Partition mapping helper for row-tiled kernels (block = 256 rows)
// ---------------------------------------------------------------------------
struct PartInfo { int part, rowbase, partEnd, localOff; const float* emb; };

__device__ __forceinline__ PartInfo get_part(int b, const float* ue, const float* ie) {
    PartInfo p;
    if (b < UB256) { p.part = 0; p.rowbase = b * 256; p.partEnd = N_USERS; p.localOff = 0; p.emb = ue; }
    else { p.part = 1; p.rowbase = N_USERS + (b - UB256) * 256; p.partEnd = N_NODES; p.localOff = N_USERS; p.emb = ie; }
    return p;
}

// ---------------------------------------------------------------------------
// kS0: S0 = emb^T emb per partition (read-only over emb), f32x2 FMAs
// ---------------------------------------------------------------------------
__global__ void __launch_bounds__(256) kS0(const float* __restrict__ user_emb,
                                           const float* __restrict__ item_emb) {
    __shared__ float sA[64 * D];
    PartInfo p = get_part(blockIdx.x, user_emb, item_emb);
    const int tid = threadIdx.x;
    const int ag = tid >> 4, bg = tid & 15;
    p4 sacc[4] = {};
    for (int t = 0; t < 4; t++) {
        const int tb = p.rowbase + t * 64;
        for (int i = tid; i < 1024; i += 256) {
            int r = i >> 4, c4 = i & 15;
            int gr = tb + r;
            float4 v = make_float4(0.f, 0.f, 0.f, 0.f);
            if (gr < p.partEnd)
                v = __ldg((const float4*)(p.emb + (size_t)(gr - p.localOff) * D + c4 * 4));
            *(float4*)(sA + r * D + c4 * 4) = v;
        }
        __syncthreads();
#pragma unroll 4
        for (int r = 0; r < 64; r++) {
            float4 a4 = *(float4*)(sA + r * D + ag * 4);
            ulonglong2 b2 = *(const ulonglong2*)(sA + r * D + bg * 4);
            u64t s;
            s = pk2(a4.x); fma2(sacc[0].lo, s, b2.x); fma2(sacc[0].hi, s, b2.y);
            s = pk2(a4.y); fma2(sacc[1].lo, s, b2.x); fma2(sacc[1].hi, s, b2.y);
            s = pk2(a4.z); fma2(sacc[2].lo, s, b2.x); fma2(sacc[2].hi, s, b2.y);
            s = pk2(a4.w); fma2(sacc[3].lo, s, b2.x); fma2(sacc[3].hi, s, b2.y);
        }
        __syncthreads();
    }
    float* Sdst = g_S + p.part * D * D;   // parity 0
#pragma unroll
    for (int j = 0; j < 4; j++)
        red_add_v4(Sdst + (ag * 4 + j) * D + bg * 4, unpk(sacc[j]));
}

// ---------------------------------------------------------------------------
// Epilogue. layer==0: hg0 = emb@M0; h1 = gcn0+hg0 -> g_h (evict_last);
//                     accumulate S1 = emb^T h1.
// layer==1: hg1 = emb@M1; h2 = gcn1+hg1; hidden_sum = emb + h1 + h2.
// ---------------------------------------------------------------------------
__global__ void __launch_bounds__(256) kEpi(const float* __restrict__ user_emb,
                                            const float* __restrict__ item_emb,
                                            const float* __restrict__ gcn,
                                            float* __restrict__ hg_out,
                                            float* __restrict__ hidden_sum,
                                            int layer) {
    __shared__ float sM[D * D];
    __shared__ float sA[64 * D];
    __shared__ float sH[64 * D];
    PartInfo p = get_part(blockIdx.x, user_emb, item_emb);
    const int tid = threadIdx.x;
    const u64t pol = mk_evict_last();
    for (int i = tid; i < D * D / 4; i += 256)
        *(float4*)(sM + i * 4) = *(const float4*)(g_M + p.part * D * D + i * 4);
    const int rg = tid >> 4, cg = tid & 15;
    const int r0 = rg * 4, c0 = cg * 4;
    p4 sacc[4] = {};
    for (int t = 0; t < 4; t++) {
        const int tb = p.rowbase + t * 64;
        for (int i = tid; i < 1024; i += 256) {
            int r = i >> 4, c4 = i & 15;
            int gr = tb + r;
            float4 v = make_float4(0.f, 0.f, 0.f, 0.f);
            if (gr < p.partEnd)
                v = __ldg((const float4*)(p.emb + (size_t)(gr - p.localOff) * D + c4 * 4));
            *(float4*)(sA + r * D + c4 * 4) = v;
        }
        __syncthreads();
        // hg tile: acc = sA(rows) @ sM, packed f32x2
        p4 acc[4] = {};
        for (int k = 0; k < D; k += 4) {
            float4 a[4]; ulonglong2 m[4];
#pragma unroll
            for (int i = 0; i < 4; i++) a[i] = *(float4*)(sA + (r0 + i) * D + k);
#pragma unroll
            for (int j = 0; j < 4; j++) m[j] = *(const ulonglong2*)(sM + (k + j) * D + c0);
#pragma unroll
            for (int i = 0; i < 4; i++) {
                u64t s;
                s = pk2(a[i].x); fma2(acc[i].lo, s, m[0].x); fma2(acc[i].hi, s, m[0].y);
                s = pk2(a[i].y); fma2(acc[i].lo, s, m[1].x); fma2(acc[i].hi, s, m[1].y);
                s = pk2(a[i].z); fma2(acc[i].lo, s, m[2].x); fma2(acc[i].hi, s, m[2].y);
                s = pk2(a[i].w); fma2(acc[i].lo, s, m[3].x); fma2(acc[i].hi, s, m[3].y);
            }
        }
#pragma unroll
        for (int i = 0; i < 4; i++) {
            int gr = tb + r0 + i;
            if (gr < p.partEnd) {
                size_t idx = (size_t)gr * D + c0;
                float4 hg = unpk(acc[i]);
                float4 g = __ldg((const float4*)(gcn + idx));
                *(float4*)(hg_out + idx) = hg;
                float4 hn = make_float4(hg.x + g.x, hg.y + g.y, hg.z + g.z, hg.w + g.w);
                if (layer == 0) {
                    st_el(g_h + idx, hn, pol);          // h1, keep resident for spmm1
                    *(float4*)(sH + (r0 + i) * D + c0) = hn;
                } else {
                    float4 h1 = __ldg((const float4*)(g_h + idx));
                    float4 e4 = *(float4*)(sA + (r0 + i) * D + c0);
                    float4 hs = make_float4(e4.x + h1.x + hn.x, e4.y + h1.y + hn.y,
                                            e4.z + h1.z + hn.z, e4.w + h1.w + hn.w);
                    *(float4*)(hidden_sum + idx) = hs;
                }
            } else if (layer == 0) {
                *(float4*)(sH + (r0 + i) * D + c0) = make_float4(0.f, 0.f, 0.f, 0.f);
            }
        }
        __syncthreads();
        if (layer == 0) {
#pragma unroll 4
            for (int r = 0; r < 64; r++) {
                float4 a4 = *(float4*)(sA + r * D + rg * 4);
                ulonglong2 h2 = *(const ulonglong2*)(sH + r * D + cg * 4);
                u64t s;
                s = pk2(a4.x); fma2(sacc[0].lo, s, h2.x); fma2(sacc[0].hi, s, h2.y);
                s = pk2(a4.y); fma2(sacc[1].lo, s, h2.x); fma2(sacc[1].hi, s, h2.y);
                s = pk2(a4.z); fma2(sacc[2].lo, s, h2.x); fma2(sacc[2].hi, s, h2.y);
                s = pk2(a4.w); fma2(sacc[3].lo, s, h2.x); fma2(sacc[3].hi, s, h2.y);
            }
            __syncthreads();
        }
    }
    if (layer == 0) {
        float* Sdst = g_S + (2 + p.part) * D * D;     // parity 1
#pragma unroll
        for (int j = 0; j < 4; j++)
            red_add_v4(Sdst + (rg * 4 + j) * D + cg * 4, unpk(sacc[j]));
    }
}

// ---------------------------------------------------------------------------
extern "C" void kernel_launch(void* const* d_in, const int* in_sizes, int n_in,
                              void* d_out, int out_size) {
    const float* user_emb = (const float*)d_in[0];
    const float* item_emb = (const float*)d_in[1];
    const float* user_w   = (const float*)d_in[2];
    const float* item_w   = (const float*)d_in[3];
    const float* adj_vals = (const float*)d_in[4];
    const int*   adj_rows = (const int*)d_in[5];
    const int*   adj_cols = (const int*)d_in[6];
    float* out = (float*)d_out;

    // d_out layout (floats): [0) hidden_sum(user_out|item_out) 19.2M
    //                        [19.2M) gcn_hidden L0,L1           38.4M
    //                        [57.6M) hgnn_hidden L0,L1          38.4M
    void* sAddr = nullptr; cudaGetSymbolAddress(&sAddr, g_S);
    cudaMemsetAsync(sAddr, 0, sizeof(float) * 2 * 2 * D * D);
    void* cAddr = nullptr; cudaGetSymbolAddress(&cAddr, g_cnt);
    cudaMemsetAsync(cAddr, 0, sizeof(int) * N_NODES);

    kP<<<2, 256>>>(user_w, item_w);

    const int EB = (NNZ_CNT + 255) / 256;   // 15625
    kHist<<<EB, 256>>>(adj_rows);
    kScanA<<<SCAN_BLOCKS, 1024>>>();
    kScanB<<<1, 512>>>();
    kScanC<<<SCAN_BLOCKS, 1024>>>();
    kScatter<<<EB, 256>>>(adj_rows, adj_cols, adj_vals);

    kS0<<<GRID_ROWS, 256>>>(user_emb, item_emb);

    float* gcn0 = out + (size_t)NODESD * 1;
    float* gcn1 = out + (size_t)NODESD * 2;
    float* hg0  = out + (size_t)NODESD * 3;
    float* hg1  = out + (size_t)NODESD * 4;

    kM<<<2, 256>>>(0);
    kSpmm0<<<(N_NODES * 32) / 256, 256>>>(user_emb, item_emb, gcn0);
    kEpi<<<GRID_ROWS, 256>>>(user_emb, item_emb, gcn0, hg0, out, 0);

    kM<<<2, 256>>>(1);
    kSpmm1<<<(N_NODES * 32) / 256, 256>>>(gcn1);
    kEpi<<<GRID_ROWS, 256>>>(user_emb, item_emb, gcn1, hg1, out, 1);
}

// round 5
// speedup vs baseline: 1.6516x; 1.2313x over previous
#include <cuda_runtime.h>
#include <cuda_fp16.h>

#define N_USERS 100000
#define N_ITEMS 200000
#define N_NODES 300000
#define D       64
#define HYPER   128
#define NNZ_CNT 4000000
#define NODESD  (N_NODES * D)        /* 19,200,000 floats */

#define UB256 391                    /* ceil(100000/256) */
#define IB256 782                    /* ceil(200000/256) */
#define GRID_ROWS (UB256 + IB256)    /* 1173 */

#define SCAN_BLOCKS 293              /* ceil(300000/1024) */

typedef unsigned long long u64t;

// Scratch (device globals: no allocations allowed)
__device__ __half g_hh[NODESD];            // fp16 gather copy: emb, then h1 (38.4 MB)
__device__ float g_P[2 * D * D];           // P_u, P_i = W Wt
__device__ float g_M[2 * D * D];           // per-layer M = P S
__device__ float g_S[2 * 2 * D * D];       // [parity][partition] S accumulators
// CSR scratch
__device__ int   g_cnt[N_NODES];           // histogram, then scatter cursor
__device__ int   g_offs[N_NODES + 1];
__device__ volatile u64t g_state[SCAN_BLOCKS];  // lookback scan state
__device__ int2  g_csr[NNZ_CNT];           // (col, val-bits) interleaved

// ---------------- packed f32x2 helpers ----------------
struct p4 { u64t lo, hi; };                // packed float4

__device__ __forceinline__ u64t pk2(float s) {
    u64t r;
    asm("mov.b64 %0, {%1,%1};" : "=l"(r) : "r"(__float_as_uint(s)));
    return r;
}
__device__ __forceinline__ void fma2(u64t& acc, u64t a, u64t b) {
    asm("fma.rn.f32x2 %0, %1, %2, %0;" : "+l"(acc) : "l"(a), "l"(b));
}
__device__ __forceinline__ float4 unpk(p4 v) {
    unsigned x, y, z, w;
    asm("mov.b64 {%0,%1}, %2;" : "=r"(x), "=r"(y) : "l"(v.lo));
    asm("mov.b64 {%0,%1}, %2;" : "=r"(z), "=r"(w) : "l"(v.hi));
    return make_float4(__uint_as_float(x), __uint_as_float(y),
                       __uint_as_float(z), __uint_as_float(w));
}

// ---------------- L2 policy helpers ----------------
__device__ __forceinline__ u64t mk_evict_last() {
    u64t pol;
    asm("createpolicy.fractional.L2::evict_last.b64 %0, 1.0;" : "=l"(pol));
    return pol;
}
__device__ __forceinline__ u64t mk_evict_first() {
    u64t pol;
    asm("createpolicy.fractional.L2::evict_first.b64 %0, 1.0;" : "=l"(pol));
    return pol;
}
__device__ __forceinline__ uint2 ld_el8(const void* p, u64t pol) {
    uint2 v;
    asm("ld.global.nc.L2::cache_hint.v2.b32 {%0,%1}, [%2], %3;"
        : "=r"(v.x), "=r"(v.y) : "l"(p), "l"(pol));
    return v;
}
__device__ __forceinline__ void st_el8(void* p, uint2 v, u64t pol) {
    asm volatile("st.global.L2::cache_hint.v2.b32 [%0], {%1,%2}, %3;"
                 :: "l"(p), "r"(v.x), "r"(v.y), "l"(pol) : "memory");
}
__device__ __forceinline__ void st_ef8(void* p, int2 v, u64t pol) {
    asm volatile("st.global.L2::cache_hint.v2.b32 [%0], {%1,%2}, %3;"
                 :: "l"(p), "r"(v.x), "r"(v.y), "l"(pol) : "memory");
}

__device__ __forceinline__ uint2 f4_to_h4(float4 v) {
    __half2 a = __floats2half2_rn(v.x, v.y);
    __half2 b = __floats2half2_rn(v.z, v.w);
    uint2 r;
    r.x = *reinterpret_cast<unsigned*>(&a);
    r.y = *reinterpret_cast<unsigned*>(&b);
    return r;
}

#define FMA4(acc, s, v) { (acc).x += (s)*(v).x; (acc).y += (s)*(v).y; \
                          (acc).z += (s)*(v).z; (acc).w += (s)*(v).w; }

__device__ __forceinline__ void red_add_v4(float* dst, float4 v) {
    asm volatile("red.global.add.v4.f32 [%0], {%1,%2,%3,%4};"
                 :: "l"(dst), "f"(v.x), "f"(v.y), "f"(v.z), "f"(v.w) : "memory");
}

// ---------------------------------------------------------------------------
// P = W @ W^T per partition. grid=(2), block=256.
// ---------------------------------------------------------------------------
__global__ void kP(const float* __restrict__ user_w, const float* __restrict__ item_w) {
    __shared__ float sW[D * 132];
    const int part = blockIdx.x;
    const float* W = (part == 0) ? user_w : item_w;
    for (int i = threadIdx.x; i < D * HYPER / 4; i += blockDim.x) {
        int r = i >> 5, c4 = i & 31;
        float4 v = __ldg((const float4*)(W + r * HYPER + c4 * 4));
        *(float4*)(sW + r * 132 + c4 * 4) = v;
    }
    __syncthreads();
    const int rg = threadIdx.x >> 4, cg = threadIdx.x & 15;
    const int r0 = rg * 4, c0 = cg * 4;
    float acc[4][4] = {};
    for (int k = 0; k < HYPER; k += 4) {
        float4 a[4], b[4];
#pragma unroll
        for (int i = 0; i < 4; i++) a[i] = *(float4*)(sW + (r0 + i) * 132 + k);
#pragma unroll
        for (int j = 0; j < 4; j++) b[j] = *(float4*)(sW + (c0 + j) * 132 + k);
#pragma unroll
        for (int i = 0; i < 4; i++)
#pragma unroll
            for (int j = 0; j < 4; j++)
                acc[i][j] += a[i].x*b[j].x + a[i].y*b[j].y + a[i].z*b[j].z + a[i].w*b[j].w;
    }
    float* Pout = g_P + part * D * D;
#pragma unroll
    for (int i = 0; i < 4; i++)
#pragma unroll
        for (int j = 0; j < 4; j++)
            Pout[(r0 + i) * D + c0 + j] = acc[i][j];
}

// ---------------------------------------------------------------------------
// M = P @ S per partition. grid=(2), block=256.
// ---------------------------------------------------------------------------
__global__ void kM(int parity) {
    __shared__ float sP[D * 68];
    __shared__ float sS[D * 68];
    const int part = blockIdx.x;
    const float* P = g_P + part * D * D;
    const float* S = g_S + (parity * 2 + part) * D * D;
    for (int i = threadIdx.x; i < D * D / 4; i += blockDim.x) {
        int r = i >> 4, c4 = i & 15;
        *(float4*)(sP + r * 68 + c4 * 4) = *(const float4*)(P + r * D + c4 * 4);
        *(float4*)(sS + r * 68 + c4 * 4) = *(const float4*)(S + r * D + c4 * 4);
    }
    __syncthreads();
    const int rg = threadIdx.x >> 4, cg = threadIdx.x & 15;
    const int r0 = rg * 4, c0 = cg * 4;
    float4 acc[4] = {};
    for (int k = 0; k < D; k += 4) {
        float4 a[4], m[4];
#pragma unroll
        for (int i = 0; i < 4; i++) a[i] = *(float4*)(sP + (r0 + i) * 68 + k);
#pragma unroll
        for (int j = 0; j < 4; j++) m[j] = *(float4*)(sS + (k + j) * 68 + c0);
#pragma unroll
        for (int i = 0; i < 4; i++) {
            FMA4(acc[i], a[i].x, m[0]); FMA4(acc[i], a[i].y, m[1]);
            FMA4(acc[i], a[i].z, m[2]); FMA4(acc[i], a[i].w, m[3]);
        }
    }
    float* Mout = g_M + part * D * D;
#pragma unroll
    for (int i = 0; i < 4; i++) *(float4*)(Mout + (r0 + i) * D + c0) = acc[i];
}

// ---------------------------------------------------------------------------
// CSR build: histogram (+ scan-state reset) -> lookback scan -> scatter
// ---------------------------------------------------------------------------
__global__ void kHist(const int* __restrict__ rows) {
    int i = blockIdx.x * blockDim.x + threadIdx.x;
    if (i < SCAN_BLOCKS) g_state[i] = 0;
    if (i < NNZ_CNT) atomicAdd(&g_cnt[__ldg(rows + i)], 1);
}

__global__ void __launch_bounds__(1024) kScan() {
    __shared__ int wsum[32];
    __shared__ int s_bt;
    __shared__ int s_run;
    const int t = threadIdx.x, bid = blockIdx.x;
    const int i = bid * 1024 + t;
    int v = (i < N_NODES) ? g_cnt[i] : 0;
    int incl = v;
#pragma unroll
    for (int d = 1; d < 32; d <<= 1) {
        int u = __shfl_up_sync(0xffffffffu, incl, d);
        if ((t & 31) >= d) incl += u;
    }
    if ((t & 31) == 31) wsum[t >> 5] = incl;
    __syncthreads();
    if (t < 32) {
        int w = wsum[t];
        int winc = w;
#pragma unroll
        for (int d = 1; d < 32; d <<= 1) {
            int u = __shfl_up_sync(0xffffffffu, winc, d);
            if (t >= d) winc += u;
        }
        wsum[t] = winc - w;            // exclusive warp offset
        if (t == 31) s_bt = winc;      // block total
    }
    __syncthreads();
    const int blockTotal = s_bt;
    if (t == 0) {
        if (bid == 0) {
            g_state[0] = ((u64t)2 << 32) | (unsigned)blockTotal;
            s_run = 0;
        } else {
            g_state[bid] = ((u64t)1 << 32) | (unsigned)blockTotal;
            __threadfence();
            int run = 0;
            int p = bid - 1;
            while (p >= 0) {
                u64t s;
                do { s = g_state[p]; } while ((s >> 32) == 0);
                run += (int)(unsigned)s;
                if ((s >> 32) == 2) break;
                p--;
            }
            g_state[bid] = ((u64t)2 << 32) | (unsigned)(run + blockTotal);
            __threadfence();
            s_run = run;
        }
    }
    __syncthreads();
    if (i < N_NODES) {
        int base = s_run + (incl - v) + wsum[t >> 5];
        g_offs[i] = base;
        g_cnt[i] = base;               // scatter cursor
    }
    if (i == 0) g_offs[N_NODES] = NNZ_CNT;
}

__global__ void kScatter(const int* __restrict__ rows, const int* __restrict__ cols,
                         const float* __restrict__ vals) {
    int i = blockIdx.x * blockDim.x + threadIdx.x;
    if (i >= NNZ_CNT) return;
    const u64t pol = mk_evict_first();
    int r = __ldg(rows + i);
    int pos = atomicAdd(&g_cnt[r], 1);
    st_ef8(&g_csr[pos], make_int2(__ldg(cols + i), __float_as_int(__ldg(vals + i))), pol);
}

// ---------------------------------------------------------------------------
// CSR SpMM over fp16 rows in g_hh (emb for layer 0, h1 for layer 1).
// One warp per row; half-warps alternate edges; 16 lanes x 4 halves = 64 cols.
// ---------------------------------------------------------------------------
__global__ void __launch_bounds__(256) kSpmm(float* __restrict__ gcn) {
    const int row = (blockIdx.x * blockDim.x + threadIdx.x) >> 5;
    if (row >= N_NODES) return;
    const int lane = threadIdx.x & 31;
    const int half = lane >> 4, l16 = lane & 15;
    const u64t pol = mk_evict_last();
    const int s = __ldg(&g_offs[row]);
    const int e = __ldg(&g_offs[row + 1]);
    float4 acc = make_float4(0.f, 0.f, 0.f, 0.f);
    for (int j = s + half; j < e; j += 2) {
        int2 cv = __ldcs(&g_csr[j]);
        float v = __int_as_float(cv.y);
        uint2 hv = ld_el8(g_hh + (size_t)cv.x * D + l16 * 4, pol);
        float2 f0 = __half22float2(*reinterpret_cast<__half2*>(&hv.x));
        float2 f1 = __half22float2(*reinterpret_cast<__half2*>(&hv.y));
        acc.x += v * f0.x; acc.y += v * f0.y; acc.z += v * f1.x; acc.w += v * f1.y;
    }
    acc.x += __shfl_xor_sync(0xffffffffu, acc.x, 16);
    acc.y += __shfl_xor_sync(0xffffffffu, acc.y, 16);
    acc.z += __shfl_xor_sync(0xffffffffu, acc.z, 16);
    acc.w += __shfl_xor_sync(0xffffffffu, acc.w, 16);
    if (half == 0)
        *(float4*)(gcn + (size_t)row * D + l16 * 4) = acc;
}

// ---------------------------------------------------------------------------
// Partition mapping helper for row-tiled kernels (block = 256 rows)
// ---------------------------------------------------------------------------
struct PartInfo { int part, rowbase, partEnd, localOff; const float* emb; };

__device__ __forceinline__ PartInfo get_part(int b, const float* ue, const float* ie) {
    PartInfo p;
    if (b < UB256) { p.part = 0; p.rowbase = b * 256; p.partEnd = N_USERS; p.localOff = 0; p.emb = ue; }
    else { p.part = 1; p.rowbase = N_USERS + (b - UB256) * 256; p.partEnd = N_NODES; p.localOff = N_USERS; p.emb = ie; }
    return p;
}

// ---------------------------------------------------------------------------
// kS0: S0 = emb^T emb per partition; also emits fp16 emb copy into g_hh
// ---------------------------------------------------------------------------
__global__ void __launch_bounds__(256) kS0(const float* __restrict__ user_emb,
                                           const float* __restrict__ item_emb) {
    __shared__ float sA[64 * D];
    PartInfo p = get_part(blockIdx.x, user_emb, item_emb);
    const int tid = threadIdx.x;
    const int ag = tid >> 4, bg = tid & 15;
    const u64t pol = mk_evict_last();
    p4 sacc[4] = {};
    for (int t = 0; t < 4; t++) {
        const int tb = p.rowbase + t * 64;
        for (int i = tid; i < 1024; i += 256) {
            int r = i >> 4, c4 = i & 15;
            int gr = tb + r;
            float4 v = make_float4(0.f, 0.f, 0.f, 0.f);
            if (gr < p.partEnd) {
                v = __ldg((const float4*)(p.emb + (size_t)(gr - p.localOff) * D + c4 * 4));
                st_el8(g_hh + (size_t)gr * D + c4 * 4, f4_to_h4(v), pol);
            }
            *(float4*)(sA + r * D + c4 * 4) = v;
        }
        __syncthreads();
#pragma unroll 4
        for (int r = 0; r < 64; r++) {
            float4 a4 = *(float4*)(sA + r * D + ag * 4);
            ulonglong2 b2 = *(const ulonglong2*)(sA + r * D + bg * 4);
            u64t s;
            s = pk2(a4.x); fma2(sacc[0].lo, s, b2.x); fma2(sacc[0].hi, s, b2.y);
            s = pk2(a4.y); fma2(sacc[1].lo, s, b2.x); fma2(sacc[1].hi, s, b2.y);
            s = pk2(a4.z); fma2(sacc[2].lo, s, b2.x); fma2(sacc[2].hi, s, b2.y);
            s = pk2(a4.w); fma2(sacc[3].lo, s, b2.x); fma2(sacc[3].hi, s, b2.y);
        }
        __syncthreads();
    }
    float* Sdst = g_S + p.part * D * D;   // parity 0
#pragma unroll
    for (int j = 0; j < 4; j++)
        red_add_v4(Sdst + (ag * 4 + j) * D + bg * 4, unpk(sacc[j]));
}

// ---------------------------------------------------------------------------
// Epilogue. layer==0: hg0 = emb@M0; h1 = gcn0+hg0 -> g_hh (fp16, evict_last);
//                     accumulate S1 = emb^T h1 (exact fp32 from smem).
// layer==1: hg1 = emb@M1; h2 = gcn1+hg1; hidden_sum = emb + h1(fp16) + h2.
// ---------------------------------------------------------------------------
__global__ void __launch_bounds__(256) kEpi(const float* __restrict__ user_emb,
                                            const float* __restrict__ item_emb,
                                            const float* __restrict__ gcn,
                                            float* __restrict__ hg_out,
                                            float* __restrict__ hidden_sum,
                                            int layer) {
    __shared__ float sM[D * D];
    __shared__ float sA[64 * D];
    __shared__ float sH[64 * D];
    PartInfo p = get_part(blockIdx.x, user_emb, item_emb);
    const int tid = threadIdx.x;
    const u64t pol = mk_evict_last();
    for (int i = tid; i < D * D / 4; i += 256)
        *(float4*)(sM + i * 4) = *(const float4*)(g_M + p.part * D * D + i * 4);
    const int rg = tid >> 4, cg = tid & 15;
    const int r0 = rg * 4, c0 = cg * 4;
    p4 sacc[4] = {};
    for (int t = 0; t < 4; t++) {
        const int tb = p.rowbase + t * 64;
        for (int i = tid; i < 1024; i += 256) {
            int r = i >> 4, c4 = i & 15;
            int gr = tb + r;
            float4 v = make_float4(0.f, 0.f, 0.f, 0.f);
            if (gr < p.partEnd)
                v = __ldg((const float4*)(p.emb + (size_t)(gr - p.localOff) * D + c4 * 4));
            *(float4*)(sA + r * D + c4 * 4) = v;
        }
        __syncthreads();
        // hg tile: acc = sA(rows) @ sM, packed f32x2
        p4 acc[4] = {};
        for (int k = 0; k < D; k += 4) {
            float4 a[4]; ulonglong2 m[4];
#pragma unroll
            for (int i = 0; i < 4; i++) a[i] = *(float4*)(sA + (r0 + i) * D + k);
#pragma unroll
            for (int j = 0; j < 4; j++) m[j] = *(const ulonglong2*)(sM + (k + j) * D + c0);
#pragma unroll
            for (int i = 0; i < 4; i++) {
                u64t s;
                s = pk2(a[i].x); fma2(acc[i].lo, s, m[0].x); fma2(acc[i].hi, s, m[0].y);
                s = pk2(a[i].y); fma2(acc[i].lo, s, m[1].x); fma2(acc[i].hi, s, m[1].y);
                s = pk2(a[i].z); fma2(acc[i].lo, s, m[2].x); fma2(acc[i].hi, s, m[2].y);
                s = pk2(a[i].w); fma2(acc[i].lo, s, m[3].x); fma2(acc[i].hi, s, m[3].y);
            }
        }
#pragma unroll
        for (int i = 0; i < 4; i++) {
            int gr = tb + r0 + i;
            if (gr < p.partEnd) {
                size_t idx = (size_t)gr * D + c0;
                float4 hg = unpk(acc[i]);
                float4 g = __ldg((const float4*)(gcn + idx));
                *(float4*)(hg_out + idx) = hg;
                float4 hn = make_float4(hg.x + g.x, hg.y + g.y, hg.z + g.z, hg.w + g.w);
                if (layer == 0) {
                    st_el8(g_hh + idx, f4_to_h4(hn), pol);   // h1 fp16, keep resident
                    *(float4*)(sH + (r0 + i) * D + c0) = hn;
                } else {
                    uint2 hu = *(const uint2*)(g_hh + idx);  // h1 fp16
                    float2 h1a = __half22float2(*reinterpret_cast<__half2*>(&hu.x));
                    float2 h1b = __half22float2(*reinterpret_cast<__half2*>(&hu.y));
                    float4 e4 = *(float4*)(sA + (r0 + i) * D + c0);
                    float4 hs = make_float4(e4.x + h1a.x + hn.x, e4.y + h1a.y + hn.y,
                                            e4.z + h1b.x + hn.z, e4.w + h1b.y + hn.w);
                    *(float4*)(hidden_sum + idx) = hs;
                }
            } else if (layer == 0) {
                *(float4*)(sH + (r0 + i) * D + c0) = make_float4(0.f, 0.f, 0.f, 0.f);
            }
        }
        __syncthreads();
        if (layer == 0) {
#pragma unroll 4
            for (int r = 0; r < 64; r++) {
                float4 a4 = *(float4*)(sA + r * D + rg * 4);
                ulonglong2 h2 = *(const ulonglong2*)(sH + r * D + cg * 4);
                u64t s;
                s = pk2(a4.x); fma2(sacc[0].lo, s, h2.x); fma2(sacc[0].hi, s, h2.y);
                s = pk2(a4.y); fma2(sacc[1].lo, s, h2.x); fma2(sacc[1].hi, s, h2.y);
                s = pk2(a4.z); fma2(sacc[2].lo, s, h2.x); fma2(sacc[2].hi, s, h2.y);
                s = pk2(a4.w); fma2(sacc[3].lo, s, h2.x); fma2(sacc[3].hi, s, h2.y);
            }
            __syncthreads();
        }
    }
    if (layer == 0) {
        float* Sdst = g_S + (2 + p.part) * D * D;     // parity 1
#pragma unroll
        for (int j = 0; j < 4; j++)
            red_add_v4(Sdst + (rg * 4 + j) * D + cg * 4, unpk(sacc[j]));
    }
}

// ---------------------------------------------------------------------------
extern "C" void kernel_launch(void* const* d_in, const int* in_sizes, int n_in,
                              void* d_out, int out_size) {
    const float* user_emb = (const float*)d_in[0];
    const float* item_emb = (const float*)d_in[1];
    const float* user_w   = (const float*)d_in[2];
    const float* item_w   = (const float*)d_in[3];
    const float* adj_vals = (const float*)d_in[4];
    const int*   adj_rows = (const int*)d_in[5];
    const int*   adj_cols = (const int*)d_in[6];
    float* out = (float*)d_out;

    // Lazily created side stream + events (first call precedes graph capture;
    // fork/join via events is graph-capture legal). No device memory involved.
    static cudaStream_t s2 = nullptr;
    static cudaEvent_t evF0 = nullptr, evJ1 = nullptr, evF2 = nullptr, evJ2 = nullptr;
    if (!s2) {
        cudaStreamCreateWithFlags(&s2, cudaStreamNonBlocking);
        cudaEventCreateWithFlags(&evF0, cudaEventDisableTiming);
        cudaEventCreateWithFlags(&evJ1, cudaEventDisableTiming);
        cudaEventCreateWithFlags(&evF2, cudaEventDisableTiming);
        cudaEventCreateWithFlags(&evJ2, cudaEventDisableTiming);
    }

    // d_out layout (floats): [0) hidden_sum(user_out|item_out) 19.2M
    //                        [19.2M) gcn_hidden L0,L1           38.4M
    //                        [57.6M) hgnn_hidden L0,L1          38.4M
    float* gcn0 = out + (size_t)NODESD * 1;
    float* gcn1 = out + (size_t)NODESD * 2;
    float* hg0  = out + (size_t)NODESD * 3;
    float* hg1  = out + (size_t)NODESD * 4;

    void* sAddr = nullptr; cudaGetSymbolAddress(&sAddr, g_S);
    void* cAddr = nullptr; cudaGetSymbolAddress(&cAddr, g_cnt);

    // ---- fork: side chain (dense prep) runs concurrently with CSR build ----
    cudaEventRecord(evF0, 0);
    cudaStreamWaitEvent(s2, evF0, 0);

    cudaMemsetAsync(sAddr, 0, sizeof(float) * 2 * 2 * D * D, s2);
    kP<<<2, 256, 0, s2>>>(user_w, item_w);
    kS0<<<GRID_ROWS, 256, 0, s2>>>(user_emb, item_emb);   // also emits fp16 emb
    kM<<<2, 256, 0, s2>>>(0);
    cudaEventRecord(evJ1, s2);

    // ---- main: CSR build ----
    cudaMemsetAsync(cAddr, 0, sizeof(int) * N_NODES);
    const int EB = (NNZ_CNT + 255) / 256;   // 15625
    kHist<<<EB, 256>>>(adj_rows);
    kScan<<<SCAN_BLOCKS, 1024>>>();
    kScatter<<<EB, 256>>>(adj_rows, adj_cols, adj_vals);

    cudaStreamWaitEvent(0, evJ1, 0);        // join: need g_hh + M0

    // ---- layer 0 ----
    kSpmm<<<(N_NODES * 32) / 256, 256>>>(gcn0);
    kEpi<<<GRID_ROWS, 256>>>(user_emb, item_emb, gcn0, hg0, out, 0);

    // kM(1) overlaps kSpmm(gcn1)
    cudaEventRecord(evF2, 0);
    cudaStreamWaitEvent(s2, evF2, 0);
    kM<<<2, 256, 0, s2>>>(1);
    cudaEventRecord(evJ2, s2);

    // ---- layer 1 ----
    kSpmm<<<(N_NODES * 32) / 256, 256>>>(gcn1);
    cudaStreamWaitEvent(0, evJ2, 0);
    kEpi<<<GRID_ROWS, 256>>>(user_emb, item_emb, gcn1, hg1, out, 1);
}